// round 11
// baseline (speedup 1.0000x reference)
#include <cuda_runtime.h>

// MeshGCN 2-layer GCN, N=100000, FEAT=16, E=3.2M.
// out_l[d] = dinv[d] * ( hs_l[d] + sum_{(s,d) in E} hs_l[s] ) + b_l
//   hs_l = (in_l @ W_l) * dinv,  dinv = rsqrt(deg_in + 1)
// Bucket adjacency (96 slots/node), one-pass build. Aggregation: warp-per-node
// with the feature record PADDED to 128B so each neighbor gather is exactly one
// cache line per LDG instruction -> 1.0 cyc/wavefront cross-LDG rate instead of
// the 2.07 cyc/wf within-LDG replay rate that capped all previous layouts.
// Lanes 16-31 read the zero padding and are discarded at the store.

#define NMAX 100000
#define F 16
#define SLOTS 96
#define SPILLMAX 8192

__device__ int    g_cnt[NMAX];
__device__ int    g_adj[NMAX * SLOTS];
__device__ int    g_spill_cnt;
__device__ int    g_spill[SPILLMAX * 2];
__device__ float  g_dinv[NMAX];
__device__ float4 g_hsp[NMAX * 8];     // 128B-stride records: 16 floats + 16 zeros
__device__ float4 g_agg[NMAX * 4];

// ---------------- zero counters ----------------
__global__ __launch_bounds__(256) void k_init(int n) {
    int i = blockIdx.x * 256 + threadIdx.x;
    if (i < n) g_cnt[i] = 0;
    if (i == 0) g_spill_cnt = 0;
}

// ---------------- one-pass bucket build: degree + placement (2 edges/thread) --
__global__ __launch_bounds__(256) void k_bucket(const int* __restrict__ src,
                                                const int* __restrict__ dst, int E) {
    int t = blockIdx.x * 256 + threadIdx.x;
    int e = t * 2;
    if (e + 1 < E) {
        int2 s2 = *reinterpret_cast<const int2*>(src + e);
        int2 d2 = *reinterpret_cast<const int2*>(dst + e);
        int p0 = atomicAdd(&g_cnt[d2.x], 1);
        int p1 = atomicAdd(&g_cnt[d2.y], 1);
        if (p0 < SLOTS) g_adj[(size_t)d2.x * SLOTS + p0] = s2.x;
        else { int sp = atomicAdd(&g_spill_cnt, 1);
               if (sp < SPILLMAX) { g_spill[2*sp] = s2.x; g_spill[2*sp+1] = d2.x; } }
        if (p1 < SLOTS) g_adj[(size_t)d2.y * SLOTS + p1] = s2.y;
        else { int sp = atomicAdd(&g_spill_cnt, 1);
               if (sp < SPILLMAX) { g_spill[2*sp] = s2.y; g_spill[2*sp+1] = d2.y; } }
    } else if (e < E) {
        int s = src[e], d = dst[e];
        int p = atomicAdd(&g_cnt[d], 1);
        if (p < SLOTS) g_adj[(size_t)d * SLOTS + p] = s;
        else { int sp = atomicAdd(&g_spill_cnt, 1);
               if (sp < SPILLMAX) { g_spill[2*sp] = s; g_spill[2*sp+1] = d; } }
    }
}

// ---------------- dense: hs = (x @ W1) * dinv into padded records -----------
__global__ __launch_bounds__(256) void k_pre1(const float* __restrict__ x,
                                              const float* __restrict__ W, int n) {
    __shared__ float sW[256];
    int tid = threadIdx.x;
    sW[tid] = W[tid];
    __syncthreads();
    int i = blockIdx.x * 256 + tid;
    if (i >= n) return;

    const float4* xp = reinterpret_cast<const float4*>(x) + (size_t)i * 4;
    float xr[16];
#pragma unroll
    for (int c = 0; c < 4; c++) {
        float4 t = xp[c];
        xr[c * 4 + 0] = t.x; xr[c * 4 + 1] = t.y;
        xr[c * 4 + 2] = t.z; xr[c * 4 + 3] = t.w;
    }
    float acc[16];
#pragma unroll
    for (int j = 0; j < 16; j++) acc[j] = 0.0f;
#pragma unroll
    for (int k = 0; k < 16; k++) {
        float xk = xr[k];
#pragma unroll
        for (int j = 0; j < 16; j++) acc[j] += xk * sW[k * 16 + j];
    }
    float dv = rsqrtf((float)(g_cnt[i] + 1));
    g_dinv[i] = dv;
#pragma unroll
    for (int c = 0; c < 4; c++) {
        float4 o;
        o.x = acc[c * 4 + 0] * dv; o.y = acc[c * 4 + 1] * dv;
        o.z = acc[c * 4 + 2] * dv; o.w = acc[c * 4 + 3] * dv;
        g_hsp[(size_t)i * 8 + c] = o;   // padding (slots 4..7) stays zero (.bss)
    }
}

// ---------------- aggregation: warp-per-node, 1 line per gather LDG ---------
// agg[node] = hs[node] + sum_{s in bucket row} hs[s]
__global__ __launch_bounds__(256) void k_agg(int n) {
    int lane = threadIdx.x & 31;
    int node = blockIdx.x * 8 + (threadIdx.x >> 5);
    if (node >= n) return;

    int raw = g_cnt[node];
    int len = raw < SLOTS ? raw : SLOTS;
    const int* row = &g_adj[(size_t)node * SLOTS];
    const float* hp = reinterpret_cast<const float*>(g_hsp);

    float acc0 = hp[(size_t)node * 32 + lane];   // seed; lanes 16-31 read zeros
    float acc1 = 0.0f;

    int base = 0;
    while (base < len) {
        int a = row[base + lane];                // coalesced 128B chunk load
        int cl = len - base; if (cl > 32) cl = 32;
        int j = 0;
        for (; j + 8 <= cl; j += 8) {
            int s0 = __shfl_sync(0xffffffffu, a, j + 0);
            int s1 = __shfl_sync(0xffffffffu, a, j + 1);
            int s2 = __shfl_sync(0xffffffffu, a, j + 2);
            int s3 = __shfl_sync(0xffffffffu, a, j + 3);
            int s4 = __shfl_sync(0xffffffffu, a, j + 4);
            int s5 = __shfl_sync(0xffffffffu, a, j + 5);
            int s6 = __shfl_sync(0xffffffffu, a, j + 6);
            int s7 = __shfl_sync(0xffffffffu, a, j + 7);
            float v0 = __ldg(hp + (size_t)s0 * 32 + lane);  // 1 line / LDG
            float v1 = __ldg(hp + (size_t)s1 * 32 + lane);
            float v2 = __ldg(hp + (size_t)s2 * 32 + lane);
            float v3 = __ldg(hp + (size_t)s3 * 32 + lane);
            float v4 = __ldg(hp + (size_t)s4 * 32 + lane);
            float v5 = __ldg(hp + (size_t)s5 * 32 + lane);
            float v6 = __ldg(hp + (size_t)s6 * 32 + lane);
            float v7 = __ldg(hp + (size_t)s7 * 32 + lane);
            acc0 += v0; acc1 += v1;
            acc0 += v2; acc1 += v3;
            acc0 += v4; acc1 += v5;
            acc0 += v6; acc1 += v7;
        }
        for (; j < cl; j++) {
            int s = __shfl_sync(0xffffffffu, a, j);
            acc0 += __ldg(hp + (size_t)s * 32 + lane);
        }
        base += 32;
    }

    // spill fold-in (normally dead: raw <= SLOTS)
    if (raw > SLOTS) {
        int m = g_spill_cnt;
        if (m > SPILLMAX) m = SPILLMAX;
        for (int i = 0; i < m; i++) {
            if (g_spill[2 * i + 1] == node) {
                int s = g_spill[2 * i];
                acc0 += __ldg(hp + (size_t)s * 32 + lane);
            }
        }
    }

    if (lane < 16)
        reinterpret_cast<float*>(g_agg)[(size_t)node * 16 + lane] = acc0 + acc1;
}

// ---------------- y = relu(dinv*agg + b1) ; hs = (y @ W2) * dinv -------------
__global__ __launch_bounds__(256) void k_mid(const float* __restrict__ W2,
                                             const float* __restrict__ b1, int n) {
    __shared__ float sW[256];
    __shared__ float sb[16];
    int tid = threadIdx.x;
    sW[tid] = W2[tid];
    if (tid < 16) sb[tid] = b1[tid];
    __syncthreads();
    int i = blockIdx.x * 256 + tid;
    if (i >= n) return;

    float dv = g_dinv[i];
    float y[16];
#pragma unroll
    for (int c = 0; c < 4; c++) {
        float4 a = g_agg[(size_t)i * 4 + c];
        float v0 = a.x * dv + sb[c * 4 + 0];
        float v1 = a.y * dv + sb[c * 4 + 1];
        float v2 = a.z * dv + sb[c * 4 + 2];
        float v3 = a.w * dv + sb[c * 4 + 3];
        y[c * 4 + 0] = v0 > 0.0f ? v0 : 0.0f;
        y[c * 4 + 1] = v1 > 0.0f ? v1 : 0.0f;
        y[c * 4 + 2] = v2 > 0.0f ? v2 : 0.0f;
        y[c * 4 + 3] = v3 > 0.0f ? v3 : 0.0f;
    }
    float acc[16];
#pragma unroll
    for (int j = 0; j < 16; j++) acc[j] = 0.0f;
#pragma unroll
    for (int k = 0; k < 16; k++) {
        float yk = y[k];
#pragma unroll
        for (int j = 0; j < 16; j++) acc[j] += yk * sW[k * 16 + j];
    }
#pragma unroll
    for (int c = 0; c < 4; c++) {
        float4 o;
        o.x = acc[c * 4 + 0] * dv; o.y = acc[c * 4 + 1] * dv;
        o.z = acc[c * 4 + 2] * dv; o.w = acc[c * 4 + 3] * dv;
        g_hsp[(size_t)i * 8 + c] = o;   // padding stays zero
    }
}

// ---------------- out = dinv*agg + b2 ----------------
__global__ __launch_bounds__(256) void k_final(const float* __restrict__ b2,
                                               float* __restrict__ out, int n) {
    __shared__ float sb[16];
    int tid = threadIdx.x;
    if (tid < 16) sb[tid] = b2[tid];
    __syncthreads();
    int i = blockIdx.x * 256 + tid;
    if (i >= n) return;

    float dv = g_dinv[i];
    float4* op = reinterpret_cast<float4*>(out) + (size_t)i * 4;
#pragma unroll
    for (int c = 0; c < 4; c++) {
        float4 a = g_agg[(size_t)i * 4 + c];
        float4 o;
        o.x = a.x * dv + sb[c * 4 + 0];
        o.y = a.y * dv + sb[c * 4 + 1];
        o.z = a.z * dv + sb[c * 4 + 2];
        o.w = a.w * dv + sb[c * 4 + 3];
        op[c] = o;
    }
}

extern "C" void kernel_launch(void* const* d_in, const int* in_sizes, int n_in,
                              void* d_out, int out_size) {
    const float* x  = (const float*)d_in[0];
    const int*   ei = (const int*)  d_in[1];
    const float* W1 = (const float*)d_in[2];
    const float* b1 = (const float*)d_in[3];
    const float* W2 = (const float*)d_in[4];
    const float* b2 = (const float*)d_in[5];
    float* out = (float*)d_out;

    int E = in_sizes[1] / 2;
    int n = in_sizes[0] / F;
    const int* src = ei;
    const int* dst = ei + E;

    int nb_n = (n + 255) / 256;
    int nb_e = (E / 2 + 255) / 256;   // 2 edges per thread
    int nb_a = (n + 7) / 8;           // warp per node, 8 warps/block

    k_init   <<<nb_n, 256>>>(n);
    k_bucket <<<nb_e, 256>>>(src, dst, E);
    k_pre1   <<<nb_n, 256>>>(x, W1, n);
    k_agg    <<<nb_a, 256>>>(n);
    k_mid    <<<nb_n, 256>>>(W2, b1, n);
    k_agg    <<<nb_a, 256>>>(n);
    k_final  <<<nb_n, 256>>>(b2, out, n);
}

// round 12
// speedup vs baseline: 1.4446x; 1.4446x over previous
#include <cuda_runtime.h>

// MeshGCN 2-layer GCN, N=100000, FEAT=16, E=3.2M.
// out_l[d] = dinv[d] * ( hs_l[d] + sum_{(s,d) in E} hs_l[s] ) + b_l
//   hs_l = (in_l @ W_l) * dinv,  dinv = rsqrt(deg_in + 1)
// Bucket adjacency (96 slots/node), one-pass build (4 edges/thread).
// Aggregation: 8 lanes/node float2 columns (4 edges per gather-LDG amortizes
// the LSU floor; 2.07 cyc/wf within-LDG is the binding cost). Width-8 shuffles
// with octet masks keep control flow legal under per-octet loop divergence.
// Low register count -> ~87% occupancy to cover L2 latency.

#define NMAX 100000
#define F 16
#define SLOTS 96
#define SPILLMAX 8192

__device__ int    g_cnt[NMAX];
__device__ int    g_adj[NMAX * SLOTS];
__device__ int    g_spill_cnt;
__device__ int    g_spill[SPILLMAX * 2];
__device__ float  g_dinv[NMAX];
__device__ float4 g_hs [NMAX * 4];
__device__ float4 g_agg[NMAX * 4];

// ---------------- zero counters ----------------
__global__ __launch_bounds__(256) void k_init(int n) {
    int i = blockIdx.x * 256 + threadIdx.x;
    if (i < n) g_cnt[i] = 0;
    if (i == 0) g_spill_cnt = 0;
}

// ---------------- one-pass bucket build (4 edges/thread) ----------------
__device__ __forceinline__ void place_edge(int s, int d) {
    int p = atomicAdd(&g_cnt[d], 1);
    if (p < SLOTS) {
        g_adj[(size_t)d * SLOTS + p] = s;
    } else {
        int sp = atomicAdd(&g_spill_cnt, 1);
        if (sp < SPILLMAX) { g_spill[2 * sp] = s; g_spill[2 * sp + 1] = d; }
    }
}

__global__ __launch_bounds__(256) void k_bucket(const int* __restrict__ src,
                                                const int* __restrict__ dst, int E) {
    int t = blockIdx.x * 256 + threadIdx.x;
    int e = t * 4;
    if (e + 4 <= E) {
        int4 s4 = *reinterpret_cast<const int4*>(src + e);
        int4 d4 = *reinterpret_cast<const int4*>(dst + e);
        place_edge(s4.x, d4.x);
        place_edge(s4.y, d4.y);
        place_edge(s4.z, d4.z);
        place_edge(s4.w, d4.w);
    } else {
        for (; e < E; e++) place_edge(src[e], dst[e]);
    }
}

// ---------------- dense: hs = (x @ W1) * dinv ----------------
__global__ __launch_bounds__(256) void k_pre1(const float* __restrict__ x,
                                              const float* __restrict__ W, int n) {
    __shared__ float sW[256];
    int tid = threadIdx.x;
    sW[tid] = W[tid];
    __syncthreads();
    int i = blockIdx.x * 256 + tid;
    if (i >= n) return;

    const float4* xp = reinterpret_cast<const float4*>(x) + (size_t)i * 4;
    float xr[16];
#pragma unroll
    for (int c = 0; c < 4; c++) {
        float4 t = xp[c];
        xr[c * 4 + 0] = t.x; xr[c * 4 + 1] = t.y;
        xr[c * 4 + 2] = t.z; xr[c * 4 + 3] = t.w;
    }
    float acc[16];
#pragma unroll
    for (int j = 0; j < 16; j++) acc[j] = 0.0f;
#pragma unroll
    for (int k = 0; k < 16; k++) {
        float xk = xr[k];
#pragma unroll
        for (int j = 0; j < 16; j++) acc[j] += xk * sW[k * 16 + j];
    }
    float dv = rsqrtf((float)(g_cnt[i] + 1));
    g_dinv[i] = dv;
#pragma unroll
    for (int c = 0; c < 4; c++) {
        float4 o;
        o.x = acc[c * 4 + 0] * dv; o.y = acc[c * 4 + 1] * dv;
        o.z = acc[c * 4 + 2] * dv; o.w = acc[c * 4 + 3] * dv;
        g_hs[(size_t)i * 4 + c] = o;
    }
}

// ---------------- aggregation: 8 lanes/node, float2, width-8 shuffles -------
// agg[node] = hs[node] + sum_{s in bucket row} hs[s]
__global__ __launch_bounds__(256) void k_agg(int n) {
    int lane  = threadIdx.x & 31;
    int o     = lane & 7;                          // float2 column (0..7)
    unsigned omask = 0xffu << (lane & 24);         // this octet's lanes
    int node  = blockIdx.x * 32 + (threadIdx.x >> 3);
    if (node >= n) return;

    int raw = g_cnt[node];
    int len = raw < SLOTS ? raw : SLOTS;
    const int* row = &g_adj[(size_t)node * SLOTS];
    const float2* hs2 = reinterpret_cast<const float2*>(g_hs);

    float2 acc0 = hs2[(size_t)node * 8 + o];       // self-loop seed
    float2 acc1 = make_float2(0.f, 0.f);

    int j = 0;
    for (; j + 8 <= len; j += 8) {
        int a = __ldg(&row[j + o]);                // octet-coalesced 32B
        int s0 = __shfl_sync(omask, a, 0, 8);
        int s1 = __shfl_sync(omask, a, 1, 8);
        int s2 = __shfl_sync(omask, a, 2, 8);
        int s3 = __shfl_sync(omask, a, 3, 8);
        int s4 = __shfl_sync(omask, a, 4, 8);
        int s5 = __shfl_sync(omask, a, 5, 8);
        int s6 = __shfl_sync(omask, a, 6, 8);
        int s7 = __shfl_sync(omask, a, 7, 8);
        float2 v0 = __ldg(&hs2[(size_t)s0 * 8 + o]);
        float2 v1 = __ldg(&hs2[(size_t)s1 * 8 + o]);
        float2 v2 = __ldg(&hs2[(size_t)s2 * 8 + o]);
        float2 v3 = __ldg(&hs2[(size_t)s3 * 8 + o]);
        float2 v4 = __ldg(&hs2[(size_t)s4 * 8 + o]);
        float2 v5 = __ldg(&hs2[(size_t)s5 * 8 + o]);
        float2 v6 = __ldg(&hs2[(size_t)s6 * 8 + o]);
        float2 v7 = __ldg(&hs2[(size_t)s7 * 8 + o]);
        acc0.x += v0.x; acc0.y += v0.y;
        acc1.x += v1.x; acc1.y += v1.y;
        acc0.x += v2.x; acc0.y += v2.y;
        acc1.x += v3.x; acc1.y += v3.y;
        acc0.x += v4.x; acc0.y += v4.y;
        acc1.x += v5.x; acc1.y += v5.y;
        acc0.x += v6.x; acc0.y += v6.y;
        acc1.x += v7.x; acc1.y += v7.y;
    }
    for (; j < len; j++) {                         // tail: broadcast within octet
        int s = __ldg(&row[j]);
        float2 v = __ldg(&hs2[(size_t)s * 8 + o]);
        acc0.x += v.x; acc0.y += v.y;
    }

    // spill fold-in (normally dead: raw <= SLOTS for every node)
    if (raw > SLOTS) {
        int m = g_spill_cnt;
        if (m > SPILLMAX) m = SPILLMAX;
        for (int i = 0; i < m; i++) {
            if (g_spill[2 * i + 1] == node) {
                int s = g_spill[2 * i];
                float2 v = __ldg(&hs2[(size_t)s * 8 + o]);
                acc0.x += v.x; acc0.y += v.y;
            }
        }
    }

    float2* agg2 = reinterpret_cast<float2*>(g_agg);
    agg2[(size_t)node * 8 + o] = make_float2(acc0.x + acc1.x, acc0.y + acc1.y);
}

// ---------------- y = relu(dinv*agg + b1) ; hs = (y @ W2) * dinv -------------
__global__ __launch_bounds__(256) void k_mid(const float* __restrict__ W2,
                                             const float* __restrict__ b1, int n) {
    __shared__ float sW[256];
    __shared__ float sb[16];
    int tid = threadIdx.x;
    sW[tid] = W2[tid];
    if (tid < 16) sb[tid] = b1[tid];
    __syncthreads();
    int i = blockIdx.x * 256 + tid;
    if (i >= n) return;

    float dv = g_dinv[i];
    float y[16];
#pragma unroll
    for (int c = 0; c < 4; c++) {
        float4 a = g_agg[(size_t)i * 4 + c];
        float v0 = a.x * dv + sb[c * 4 + 0];
        float v1 = a.y * dv + sb[c * 4 + 1];
        float v2 = a.z * dv + sb[c * 4 + 2];
        float v3 = a.w * dv + sb[c * 4 + 3];
        y[c * 4 + 0] = v0 > 0.0f ? v0 : 0.0f;
        y[c * 4 + 1] = v1 > 0.0f ? v1 : 0.0f;
        y[c * 4 + 2] = v2 > 0.0f ? v2 : 0.0f;
        y[c * 4 + 3] = v3 > 0.0f ? v3 : 0.0f;
    }
    float acc[16];
#pragma unroll
    for (int j = 0; j < 16; j++) acc[j] = 0.0f;
#pragma unroll
    for (int k = 0; k < 16; k++) {
        float yk = y[k];
#pragma unroll
        for (int j = 0; j < 16; j++) acc[j] += yk * sW[k * 16 + j];
    }
#pragma unroll
    for (int c = 0; c < 4; c++) {
        float4 o;
        o.x = acc[c * 4 + 0] * dv; o.y = acc[c * 4 + 1] * dv;
        o.z = acc[c * 4 + 2] * dv; o.w = acc[c * 4 + 3] * dv;
        g_hs[(size_t)i * 4 + c] = o;
    }
}

// ---------------- out = dinv*agg + b2 ----------------
__global__ __launch_bounds__(256) void k_final(const float* __restrict__ b2,
                                               float* __restrict__ out, int n) {
    __shared__ float sb[16];
    int tid = threadIdx.x;
    if (tid < 16) sb[tid] = b2[tid];
    __syncthreads();
    int i = blockIdx.x * 256 + tid;
    if (i >= n) return;

    float dv = g_dinv[i];
    float4* op = reinterpret_cast<float4*>(out) + (size_t)i * 4;
#pragma unroll
    for (int c = 0; c < 4; c++) {
        float4 a = g_agg[(size_t)i * 4 + c];
        float4 o;
        o.x = a.x * dv + sb[c * 4 + 0];
        o.y = a.y * dv + sb[c * 4 + 1];
        o.z = a.z * dv + sb[c * 4 + 2];
        o.w = a.w * dv + sb[c * 4 + 3];
        op[c] = o;
    }
}

extern "C" void kernel_launch(void* const* d_in, const int* in_sizes, int n_in,
                              void* d_out, int out_size) {
    const float* x  = (const float*)d_in[0];
    const int*   ei = (const int*)  d_in[1];
    const float* W1 = (const float*)d_in[2];
    const float* b1 = (const float*)d_in[3];
    const float* W2 = (const float*)d_in[4];
    const float* b2 = (const float*)d_in[5];
    float* out = (float*)d_out;

    int E = in_sizes[1] / 2;
    int n = in_sizes[0] / F;
    const int* src = ei;
    const int* dst = ei + E;

    int nb_n = (n + 255) / 256;
    int nb_e = (E / 4 + 255) / 256;   // 4 edges per thread
    int nb_a = (n + 31) / 32;         // 32 nodes per 256-thread block

    k_init   <<<nb_n, 256>>>(n);
    k_bucket <<<nb_e, 256>>>(src, dst, E);
    k_pre1   <<<nb_n, 256>>>(x, W1, n);
    k_agg    <<<nb_a, 256>>>(n);
    k_mid    <<<nb_n, 256>>>(W2, b1, n);
    k_agg    <<<nb_a, 256>>>(n);
    k_final  <<<nb_n, 256>>>(b2, out, n);
}

// round 15
// speedup vs baseline: 1.5923x; 1.1022x over previous
#include <cuda_runtime.h>

// MeshGCN 2-layer GCN, N=100000, FEAT=16, E=3.2M.
// out_l[d] = dinv[d] * ( hs_l[d] + sum_{(s,d) in E} hs_l[s] ) + b_l
//   hs_l = (in_l @ W_l) * dinv,  dinv = rsqrt(deg_in + 1)
// Bucket adjacency (96 slots/node), one-pass build (4 edges/thread).
// Aggregation: 8 lanes/node float2 columns; gather wall = 2.07 cyc/wf.
// Fused epilogues with DOUBLE-BUFFERED features (fixes R12's read/write race:
// a kernel never writes the array it gathers from):
//   agg_mid: gather g_hsA -> relu(dinv*acc+b1) -> octet-shuffle 16x16 matmul
//            -> write g_hsB
//   agg_out: gather g_hsB -> dinv*acc + b2 -> write out; clears g_cnt
// 5 launches total.

#define NMAX 100000
#define F 16
#define SLOTS 96
#define SPILLMAX 8192

__device__ int    g_cnt[NMAX];          // zero at entry (.bss first, cleared by agg_out)
__device__ int    g_adj[NMAX * SLOTS];
__device__ int    g_spill_cnt;
__device__ int    g_spill[SPILLMAX * 2];
__device__ float  g_dinv[NMAX];
__device__ float4 g_hsA[NMAX * 4];      // layer-1 features
__device__ float4 g_hsB[NMAX * 4];      // layer-2 features

// ---------------- tiny init: spill counter only ----------------
__global__ void k_init() {
    if (threadIdx.x == 0) g_spill_cnt = 0;
}

// ---------------- one-pass bucket build (4 edges/thread) ----------------
__device__ __forceinline__ void place_edge(int s, int d) {
    int p = atomicAdd(&g_cnt[d], 1);
    if (p < SLOTS) {
        g_adj[(size_t)d * SLOTS + p] = s;
    } else {
        int sp = atomicAdd(&g_spill_cnt, 1);
        if (sp < SPILLMAX) { g_spill[2 * sp] = s; g_spill[2 * sp + 1] = d; }
    }
}

__global__ __launch_bounds__(256) void k_bucket(const int* __restrict__ src,
                                                const int* __restrict__ dst, int E) {
    int t = blockIdx.x * 256 + threadIdx.x;
    int e = t * 4;
    if (e + 4 <= E) {
        int4 s4 = *reinterpret_cast<const int4*>(src + e);
        int4 d4 = *reinterpret_cast<const int4*>(dst + e);
        place_edge(s4.x, d4.x);
        place_edge(s4.y, d4.y);
        place_edge(s4.z, d4.z);
        place_edge(s4.w, d4.w);
    } else {
        for (; e < E; e++) place_edge(src[e], dst[e]);
    }
}

// ---------------- dense: hsA = (x @ W1) * dinv ; dinv stored ----------------
__global__ __launch_bounds__(256) void k_pre1(const float* __restrict__ x,
                                              const float* __restrict__ W, int n) {
    __shared__ float sW[256];
    int tid = threadIdx.x;
    sW[tid] = W[tid];
    __syncthreads();
    int i = blockIdx.x * 256 + tid;
    if (i >= n) return;

    const float4* xp = reinterpret_cast<const float4*>(x) + (size_t)i * 4;
    float xr[16];
#pragma unroll
    for (int c = 0; c < 4; c++) {
        float4 t = xp[c];
        xr[c * 4 + 0] = t.x; xr[c * 4 + 1] = t.y;
        xr[c * 4 + 2] = t.z; xr[c * 4 + 3] = t.w;
    }
    float acc[16];
#pragma unroll
    for (int j = 0; j < 16; j++) acc[j] = 0.0f;
#pragma unroll
    for (int k = 0; k < 16; k++) {
        float xk = xr[k];
#pragma unroll
        for (int j = 0; j < 16; j++) acc[j] += xk * sW[k * 16 + j];
    }
    float dv = rsqrtf((float)(g_cnt[i] + 1));
    g_dinv[i] = dv;
#pragma unroll
    for (int c = 0; c < 4; c++) {
        float4 o;
        o.x = acc[c * 4 + 0] * dv; o.y = acc[c * 4 + 1] * dv;
        o.z = acc[c * 4 + 2] * dv; o.w = acc[c * 4 + 3] * dv;
        g_hsA[(size_t)i * 4 + c] = o;
    }
}

// ---------------- shared gather core: 8 lanes/node, predicated batches ------
// acc = hs[node] + sum_{neighbors} hs[s]  (this lane's float2 column)
__device__ __forceinline__ float2 gather_node(const float2* __restrict__ hs2,
                                              int node, int o, unsigned omask,
                                              int raw) {
    int len = raw < SLOTS ? raw : SLOTS;
    const int* row = &g_adj[(size_t)node * SLOTS];

    float2 acc0 = hs2[(size_t)node * 8 + o];       // self-loop seed
    float2 acc1 = make_float2(0.f, 0.f);

    for (int j = 0; j < len; j += 8) {
        int a = __ldg(&row[j + o]);                // octet-coalesced 32B
        int s0 = __shfl_sync(omask, a, 0, 8);
        int s1 = __shfl_sync(omask, a, 1, 8);
        int s2 = __shfl_sync(omask, a, 2, 8);
        int s3 = __shfl_sync(omask, a, 3, 8);
        int s4 = __shfl_sync(omask, a, 4, 8);
        int s5 = __shfl_sync(omask, a, 5, 8);
        int s6 = __shfl_sync(omask, a, 6, 8);
        int s7 = __shfl_sync(omask, a, 7, 8);
        // Stale slots hold valid node ids (zeros on first run); loads are safe,
        // contributions masked below.
        float2 v0 = __ldg(&hs2[(size_t)s0 * 8 + o]);
        float2 v1 = __ldg(&hs2[(size_t)s1 * 8 + o]);
        float2 v2 = __ldg(&hs2[(size_t)s2 * 8 + o]);
        float2 v3 = __ldg(&hs2[(size_t)s3 * 8 + o]);
        float2 v4 = __ldg(&hs2[(size_t)s4 * 8 + o]);
        float2 v5 = __ldg(&hs2[(size_t)s5 * 8 + o]);
        float2 v6 = __ldg(&hs2[(size_t)s6 * 8 + o]);
        float2 v7 = __ldg(&hs2[(size_t)s7 * 8 + o]);
        if (j + 0 < len) { acc0.x += v0.x; acc0.y += v0.y; }
        if (j + 1 < len) { acc1.x += v1.x; acc1.y += v1.y; }
        if (j + 2 < len) { acc0.x += v2.x; acc0.y += v2.y; }
        if (j + 3 < len) { acc1.x += v3.x; acc1.y += v3.y; }
        if (j + 4 < len) { acc0.x += v4.x; acc0.y += v4.y; }
        if (j + 5 < len) { acc1.x += v5.x; acc1.y += v5.y; }
        if (j + 6 < len) { acc0.x += v6.x; acc0.y += v6.y; }
        if (j + 7 < len) { acc1.x += v7.x; acc1.y += v7.y; }
    }

    if (raw > SLOTS) {                             // spill fold-in (normally dead)
        int m = g_spill_cnt;
        if (m > SPILLMAX) m = SPILLMAX;
        for (int i = 0; i < m; i++) {
            if (g_spill[2 * i + 1] == node) {
                int s = g_spill[2 * i];
                float2 v = __ldg(&hs2[(size_t)s * 8 + o]);
                acc0.x += v.x; acc0.y += v.y;
            }
        }
    }
    return make_float2(acc0.x + acc1.x, acc0.y + acc1.y);
}

// ---- agg_mid: gather hsA; y=relu(dinv*acc+b1); hsB=(y@W2)*dinv --------------
__global__ __launch_bounds__(256) void k_agg_mid(const float* __restrict__ W2,
                                                 const float* __restrict__ b1, int n) {
    __shared__ float sW[256];
    sW[threadIdx.x] = W2[threadIdx.x];
    __syncthreads();

    int lane  = threadIdx.x & 31;
    int o     = lane & 7;
    unsigned omask = 0xffu << (lane & 24);
    int node  = blockIdx.x * 32 + (threadIdx.x >> 3);
    if (node >= n) return;

    int raw = g_cnt[node];
    float2 acc = gather_node(reinterpret_cast<const float2*>(g_hsA),
                             node, o, omask, raw);

    float dv = g_dinv[node];
    float y0 = acc.x * dv + __ldg(&b1[2 * o]);
    float y1 = acc.y * dv + __ldg(&b1[2 * o + 1]);
    y0 = y0 > 0.0f ? y0 : 0.0f;
    y1 = y1 > 0.0f ? y1 : 0.0f;

    // h[j] = sum_k y[k] * W2[k][j] for j = 2o, 2o+1; y spread 2-per-lane
    float h0 = 0.0f, h1 = 0.0f;
#pragma unroll
    for (int k8 = 0; k8 < 8; k8++) {
        float ya = __shfl_sync(omask, y0, k8, 8);
        float yb = __shfl_sync(omask, y1, k8, 8);
        h0 += ya * sW[(2 * k8) * 16 + 2 * o]     + yb * sW[(2 * k8 + 1) * 16 + 2 * o];
        h1 += ya * sW[(2 * k8) * 16 + 2 * o + 1] + yb * sW[(2 * k8 + 1) * 16 + 2 * o + 1];
    }
    reinterpret_cast<float2*>(g_hsB)[(size_t)node * 8 + o] =
        make_float2(h0 * dv, h1 * dv);
}

// ---- agg_out: gather hsB; out = dinv*acc + b2 ; clear g_cnt -----------------
__global__ __launch_bounds__(256) void k_agg_out(const float* __restrict__ b2,
                                                 float* __restrict__ out, int n) {
    int lane  = threadIdx.x & 31;
    int o     = lane & 7;
    unsigned omask = 0xffu << (lane & 24);
    int node  = blockIdx.x * 32 + (threadIdx.x >> 3);
    if (node >= n) return;

    int raw = g_cnt[node];
    float2 acc = gather_node(reinterpret_cast<const float2*>(g_hsB),
                             node, o, omask, raw);

    float dv = g_dinv[node];
    float2 r = make_float2(acc.x * dv + __ldg(&b2[2 * o]),
                           acc.y * dv + __ldg(&b2[2 * o + 1]));
    reinterpret_cast<float2*>(out)[(size_t)node * 8 + o] = r;

    if (o == 0) g_cnt[node] = 0;    // restore invariant for the next call
}

extern "C" void kernel_launch(void* const* d_in, const int* in_sizes, int n_in,
                              void* d_out, int out_size) {
    const float* x  = (const float*)d_in[0];
    const int*   ei = (const int*)  d_in[1];
    const float* W1 = (const float*)d_in[2];
    const float* b1 = (const float*)d_in[3];
    const float* W2 = (const float*)d_in[4];
    const float* b2 = (const float*)d_in[5];
    float* out = (float*)d_out;

    int E = in_sizes[1] / 2;
    int n = in_sizes[0] / F;
    const int* src = ei;
    const int* dst = ei + E;

    int nb_n = (n + 255) / 256;
    int nb_e = (E / 4 + 255) / 256;   // 4 edges per thread
    int nb_a = (n + 31) / 32;         // 32 nodes per 256-thread block

    k_init    <<<1,    32>>>();
    k_bucket  <<<nb_e, 256>>>(src, dst, E);
    k_pre1    <<<nb_n, 256>>>(x, W1, n);
    k_agg_mid <<<nb_a, 256>>>(W2, b1, n);
    k_agg_out <<<nb_a, 256>>>(b2, out, n);
}